// round 7
// baseline (speedup 1.0000x reference)
#include <cuda_runtime.h>
#include <cuda_bf16.h>
#include <math.h>
#include <stdint.h>

#define D_MODEL 256
#define N_HEADS 8
#define HEAD_DIM 32
#define BATCH 8
#define SEQ 2048
#define M_TOTAL (BATCH * SEQ)  // 16384

// Scratch (alloc-free rule: __device__ globals)
__device__ float g_Q[M_TOTAL * D_MODEL];
__device__ float g_K[M_TOTAL * D_MODEL];   // compacted keys
__device__ float g_V[M_TOTAL * D_MODEL];   // compacted values
__device__ float g_O[M_TOTAL * D_MODEL];
__device__ int g_pos[SEQ];                 // token -> compact slot (-1 = masked)
__device__ int g_cnt[1];                   // number of kept keys

// ---------------------------------------------------------------------------
// helpers
// ---------------------------------------------------------------------------
__device__ __forceinline__ uint32_t f2tf(float x) {
    uint32_t r;
    asm("cvt.rna.tf32.f32 %0, %1;" : "=r"(r) : "f"(x));
    return r;
}

__device__ __forceinline__ void mma_tf32(float* c, uint32_t a0, uint32_t a1,
                                         uint32_t a2, uint32_t a3,
                                         uint32_t b0, uint32_t b1) {
    asm volatile(
        "mma.sync.aligned.m16n8k8.row.col.f32.tf32.tf32.f32 "
        "{%0,%1,%2,%3}, {%4,%5,%6,%7}, {%8,%9}, {%0,%1,%2,%3};"
        : "+f"(c[0]), "+f"(c[1]), "+f"(c[2]), "+f"(c[3])
        : "r"(a0), "r"(a1), "r"(a2), "r"(a3), "r"(b0), "r"(b1));
}

__device__ __forceinline__ void mma_bf16(float* c, uint32_t a0, uint32_t a1,
                                         uint32_t a2, uint32_t a3,
                                         uint32_t b0, uint32_t b1) {
    asm volatile(
        "mma.sync.aligned.m16n8k16.row.col.f32.bf16.bf16.f32 "
        "{%0,%1,%2,%3}, {%4,%5,%6,%7}, {%8,%9}, {%0,%1,%2,%3};"
        : "+f"(c[0]), "+f"(c[1]), "+f"(c[2]), "+f"(c[3])
        : "r"(a0), "r"(a1), "r"(a2), "r"(a3), "r"(b0), "r"(b1));
}

// prmt: pack high halves of two f32 -> bf16x2 (lo arg -> low half)
__device__ __forceinline__ uint32_t prmt_hi(float lo, float hi) {
    uint32_t r;
    asm("prmt.b32 %0, %1, %2, 0x7632;"
        : "=r"(r) : "r"(__float_as_uint(lo)), "r"(__float_as_uint(hi)));
    return r;
}

__device__ __forceinline__ float ex2(float x) {
    float r;
    asm("ex2.approx.ftz.f32 %0, %1;" : "=f"(r) : "f"(x));
    return r;
}

__device__ __forceinline__ float trunc_bf(float x) {
    return __uint_as_float(__float_as_uint(x) & 0xFFFF0000u);
}

// ---------------------------------------------------------------------------
// Mask scan: pos[s] = compact index for kept keys (-1 masked), cnt = total.
// ---------------------------------------------------------------------------
__global__ __launch_bounds__(256) void scan_mask(const float* __restrict__ m,
                                                 int* __restrict__ pos,
                                                 int* __restrict__ cnt) {
    __shared__ int warpsum[8];
    const int tid = threadIdx.x;
    int keep[8], local[8], s = 0;
#pragma unroll
    for (int i = 0; i < 8; i++) {
        keep[i] = (m[tid * 8 + i] == 0.0f) ? 1 : 0;
        local[i] = s;
        s += keep[i];
    }
    const int lane = tid & 31, w = tid >> 5;
    int x = s;
#pragma unroll
    for (int d = 1; d < 32; d <<= 1) {
        int y = __shfl_up_sync(0xffffffffu, x, d);
        if (lane >= d) x += y;
    }
    if (lane == 31) warpsum[w] = x;
    __syncthreads();
    if (tid == 0) {
        int a = 0;
#pragma unroll
        for (int i = 0; i < 8; i++) {
            int t = warpsum[i];
            warpsum[i] = a;
            a += t;
        }
        *cnt = a;
    }
    __syncthreads();
    const int off = warpsum[w] + x - s;
#pragma unroll
    for (int i = 0; i < 8; i++)
        pos[tid * 8 + i] = keep[i] ? off + local[i] : -1;
}

// ---------------------------------------------------------------------------
// GEMM: C[M,256] = A[M,256] @ W[256,256] + bias.
// 2-term split: A tf32(rna), W = trunc-bf16-hi (exact tf32) + rna-tf32 lo.
// W tile column-swizzled ((c&7)*8+(c>>3)) so each frag fetch is LDS.128
// covering two n-chunks. Block tile 128x64, k-stage 32, 4 warps.
// blockIdx.z selects one of up to 3 fused problem instances.
// ---------------------------------------------------------------------------
struct GemmArgs {
    const float* A;
    const float* W;
    const float* bias;
    float* C;
    const int* remap;
};
struct GemmArgs3 {
    GemmArgs p[3];
};

__global__ __launch_bounds__(128) void gemm_tf32(GemmArgs3 args) {
    const GemmArgs P = args.p[blockIdx.z];
    const float* __restrict__ A = P.A;
    const float* __restrict__ W = P.W;
    const float* __restrict__ bias = P.bias;
    float* __restrict__ C = P.C;
    const int* __restrict__ remap = P.remap;

    __shared__ float As[128][36];    // [m][k] tf32, stride 36
    __shared__ float2 Wd[32][70];    // [k][n-swizzled] (hi,lo), stride 70

    const int tid = threadIdx.x;
    const int lane = tid & 31;
    const int wid = tid >> 5;
    const int g = lane >> 2;
    const int tg = lane & 3;

    const int m0 = blockIdx.y * 128;
    const int n0 = blockIdx.x * 64;

    float acc[2][8][4];
#pragma unroll
    for (int f = 0; f < 2; f++)
#pragma unroll
        for (int nc = 0; nc < 8; nc++)
#pragma unroll
            for (int i = 0; i < 4; i++) acc[f][nc][i] = 0.f;

    for (int k0 = 0; k0 < 256; k0 += 32) {
        __syncthreads();
        // A tile: 128 rows x 32 k = 1024 float4, 8 per thread
#pragma unroll
        for (int i = 0; i < 8; i++) {
            int f = tid + i * 128;
            int r = f >> 3, c4 = (f & 7) * 4;
            float4 va = *(const float4*)(A + (size_t)(m0 + r) * 256 + k0 + c4);
            As[r][c4 + 0] = __uint_as_float(f2tf(va.x));
            As[r][c4 + 1] = __uint_as_float(f2tf(va.y));
            As[r][c4 + 2] = __uint_as_float(f2tf(va.z));
            As[r][c4 + 3] = __uint_as_float(f2tf(va.w));
        }
        // W tile: 32 k-rows x 64 n, hi/lo split, column-swizzled
#pragma unroll
        for (int i = 0; i < 4; i++) {
            int f = tid + i * 128;
            int rw = f >> 4, cw = (f & 15) * 4;
            float4 vw = *(const float4*)(W + (size_t)(k0 + rw) * 256 + n0 + cw);
#pragma unroll
            for (int e = 0; e < 4; e++) {
                float w = (e == 0) ? vw.x : (e == 1) ? vw.y : (e == 2) ? vw.z : vw.w;
                float wh = trunc_bf(w);
                int c = cw + e;
                Wd[rw][(c & 7) * 8 + (c >> 3)] =
                    make_float2(wh, __uint_as_float(f2tf(w - wh)));
            }
        }
        __syncthreads();

#pragma unroll
        for (int kc = 0; kc < 4; kc++) {
            uint32_t a[2][4];
#pragma unroll
            for (int f = 0; f < 2; f++) {
                int r = wid * 32 + f * 16 + g;
                a[f][0] = __float_as_uint(As[r][kc * 8 + tg]);
                a[f][1] = __float_as_uint(As[r + 8][kc * 8 + tg]);
                a[f][2] = __float_as_uint(As[r][kc * 8 + tg + 4]);
                a[f][3] = __float_as_uint(As[r + 8][kc * 8 + tg + 4]);
            }
#pragma unroll
            for (int ncp = 0; ncp < 4; ncp++) {
                // cols g*8 + 2ncp, +1 -> (hi,lo) for nc=2ncp and 2ncp+1 at col g
                float4 w0 = *(const float4*)&Wd[kc * 8 + tg][g * 8 + 2 * ncp];
                float4 w1 = *(const float4*)&Wd[kc * 8 + tg + 4][g * 8 + 2 * ncp];
#pragma unroll
                for (int f = 0; f < 2; f++) {
                    mma_tf32(acc[f][2 * ncp], a[f][0], a[f][1], a[f][2], a[f][3],
                             __float_as_uint(w0.y), __float_as_uint(w1.y));
                    mma_tf32(acc[f][2 * ncp], a[f][0], a[f][1], a[f][2], a[f][3],
                             __float_as_uint(w0.x), __float_as_uint(w1.x));
                    mma_tf32(acc[f][2 * ncp + 1], a[f][0], a[f][1], a[f][2], a[f][3],
                             __float_as_uint(w0.w), __float_as_uint(w1.w));
                    mma_tf32(acc[f][2 * ncp + 1], a[f][0], a[f][1], a[f][2], a[f][3],
                             __float_as_uint(w0.z), __float_as_uint(w1.z));
                }
            }
        }
    }

#pragma unroll
    for (int f = 0; f < 2; f++) {
        int r0 = m0 + wid * 32 + f * 16 + g;
        int r1 = r0 + 8;
        int d0 = r0, d1 = r1;
        bool st0 = true, st1 = true;
        if (remap) {
            int p0 = __ldg(remap + (r0 & (SEQ - 1)));
            int p1 = __ldg(remap + (r1 & (SEQ - 1)));
            st0 = p0 >= 0;
            st1 = p1 >= 0;
            d0 = (r0 & ~(SEQ - 1)) + p0;
            d1 = (r1 & ~(SEQ - 1)) + p1;
        }
#pragma unroll
        for (int nc = 0; nc < 8; nc++) {
            int col = n0 + nc * 8 + tg * 2;
            float2 bv = *(const float2*)(bias + col);
            if (st0)
                *(float2*)(C + (size_t)d0 * 256 + col) =
                    make_float2(acc[f][nc][0] + bv.x, acc[f][nc][1] + bv.y);
            if (st1)
                *(float2*)(C + (size_t)d1 * 256 + col) =
                    make_float2(acc[f][nc][2] + bv.x, acc[f][nc][3] + bv.y);
        }
    }
}

// ---------------------------------------------------------------------------
// Flash attention over COMPACTED keys, no online softmax.
// Per-pc (16-key) pipeline: score -> exp -> trunc-split pack -> PV, keeping
// only 8+8 live registers for scores/P. Truncation split via PRMT (no CVTs).
// grid = (S/128, B*H), block = 128 (4 warps). Warp: 32 queries (2 m16 frags).
// ---------------------------------------------------------------------------
__global__ __launch_bounds__(128) void flash_mma(const float* __restrict__ Q,
                                                 const float* __restrict__ K,
                                                 const float* __restrict__ V,
                                                 const int* __restrict__ cntp,
                                                 float* __restrict__ O) {
    __shared__ float Ks[64][40];        // [key][dim-permuted] tf32
    __shared__ uint16_t Vd[32][160];    // [dim][key-quad: 4 hi, 4 lo] bf16 bits

    const int tid = threadIdx.x;
    const int lane = tid & 31;
    const int wid = tid >> 5;
    const int g = lane >> 2;
    const int tg = lane & 3;

    const int qt = blockIdx.x;          // 128-query tile
    const int b = blockIdx.y >> 3;
    const int h = blockIdx.y & 7;

    const int cnt = __ldg(cntp);
    const int nt = (cnt + 63) >> 6;

    const float LOG2E = 1.4426950408889634f;
    const float qscale = 0.17677669529663687f * LOG2E;  // 1/sqrt(32)*log2(e)

    // Q fragments (2 M-frags per warp, pre-scaled, tf32)
    uint32_t qf[2][4][4];
#pragma unroll
    for (int f = 0; f < 2; f++) {
        const float* qb = Q +
            (size_t)(b * SEQ + qt * 128 + wid * 32 + f * 16) * D_MODEL + h * HEAD_DIM;
#pragma unroll
        for (int kc = 0; kc < 4; kc++) {
            qf[f][kc][0] = f2tf(qb[(size_t)g * D_MODEL + kc * 8 + tg] * qscale);
            qf[f][kc][1] = f2tf(qb[(size_t)(g + 8) * D_MODEL + kc * 8 + tg] * qscale);
            qf[f][kc][2] = f2tf(qb[(size_t)g * D_MODEL + kc * 8 + tg + 4] * qscale);
            qf[f][kc][3] = f2tf(qb[(size_t)(g + 8) * D_MODEL + kc * 8 + tg + 4] * qscale);
        }
    }

    float o[2][4][4];
#pragma unroll
    for (int f = 0; f < 2; f++)
#pragma unroll
        for (int i = 0; i < 4; i++)
#pragma unroll
            for (int j = 0; j < 4; j++) o[f][i][j] = 0.f;
    float lr[2][2] = {{0.f, 0.f}, {0.f, 0.f}};

    const float* kbase = K + (size_t)b * SEQ * D_MODEL + h * HEAD_DIM;
    const float* vbase = V + (size_t)b * SEQ * D_MODEL + h * HEAD_DIM;

    for (int t = 0; t < nt; t++) {
        __syncthreads();
#pragma unroll
        for (int i = 0; i < 4; i++) {
            int f = tid + i * 128;
            int r = f >> 3, c4 = (f & 7) * 4;
            int key = t * 64 + r;
            float4 kv = make_float4(0.f, 0.f, 0.f, 0.f);
            float4 vv = make_float4(0.f, 0.f, 0.f, 0.f);
            if (key < cnt) {
                kv = *(const float4*)(kbase + (size_t)key * D_MODEL + c4);
                vv = *(const float4*)(vbase + (size_t)key * D_MODEL + c4);
            }
            // K: dim-pair permute: col'(d) = (d&~7) + 2*(d&3) + ((d>>2)&1)
            {
                int hb = (c4 >> 2) & 1;
                int cb = (c4 & ~7) + hb;
                Ks[r][cb + 0] = __uint_as_float(f2tf(kv.x));
                Ks[r][cb + 2] = __uint_as_float(f2tf(kv.y));
                Ks[r][cb + 4] = __uint_as_float(f2tf(kv.z));
                Ks[r][cb + 6] = __uint_as_float(f2tf(kv.w));
            }
            // V: key-permuted column, trunc hi/lo quads (bf16 bits)
            int u = r & 15;
            int col = (r >> 4) * 16 + ((u >> 1) & 3) * 4 + (u & 1) + ((u >> 3) & 1) * 2;
            int nh = (col >> 4) * 32 + (((col >> 2) & 3)) * 8 + (col & 3);
            float vx[4] = {vv.x, vv.y, vv.z, vv.w};
#pragma unroll
            for (int e = 0; e < 4; e++) {
                uint32_t bits = __float_as_uint(vx[e]);
                Vd[c4 + e][nh] = (uint16_t)(bits >> 16);
                float lo = vx[e] - __uint_as_float(bits & 0xFFFF0000u);
                Vd[c4 + e][nh + 4] = (uint16_t)(__float_as_uint(lo) >> 16);
            }
        }
        __syncthreads();

        const bool fix = (t == nt - 1) && (cnt & 63);
#pragma unroll
        for (int f = 0; f < 2; f++) {
#pragma unroll
            for (int pc = 0; pc < 4; pc++) {
                // --- scores for n-chunks 2pc, 2pc+1 ---
                float s0[4] = {0.f, 0.f, 0.f, 0.f};
                float s1[4] = {0.f, 0.f, 0.f, 0.f};
#pragma unroll
                for (int kc = 0; kc < 4; kc++) {
                    uint2 k0 = *(const uint2*)&Ks[(2 * pc) * 8 + g][kc * 8 + tg * 2];
                    mma_tf32(s0, qf[f][kc][0], qf[f][kc][1], qf[f][kc][2],
                             qf[f][kc][3], k0.x, k0.y);
                    uint2 k1 = *(const uint2*)&Ks[(2 * pc + 1) * 8 + g][kc * 8 + tg * 2];
                    mma_tf32(s1, qf[f][kc][0], qf[f][kc][1], qf[f][kc][2],
                             qf[f][kc][3], k1.x, k1.y);
                }
                if (fix) {
                    int key0 = t * 64 + (2 * pc) * 8 + tg * 2;
                    if (key0 >= cnt) { s0[0] = -1e30f; s0[2] = -1e30f; }
                    if (key0 + 1 >= cnt) { s0[1] = -1e30f; s0[3] = -1e30f; }
                    int key1 = key0 + 8;
                    if (key1 >= cnt) { s1[0] = -1e30f; s1[2] = -1e30f; }
                    if (key1 + 1 >= cnt) { s1[1] = -1e30f; s1[3] = -1e30f; }
                }
                // --- exp + trunc-split pack ---
                float e00 = ex2(s0[0]), e01 = ex2(s0[1]);
                float e02 = ex2(s0[2]), e03 = ex2(s0[3]);
                float e10 = ex2(s1[0]), e11 = ex2(s1[1]);
                float e12 = ex2(s1[2]), e13 = ex2(s1[3]);
                lr[f][0] += e00 + e01 + e10 + e11;
                lr[f][1] += e02 + e03 + e12 + e13;
                uint32_t ph0 = prmt_hi(e00, e01);
                uint32_t ph1 = prmt_hi(e02, e03);
                uint32_t ph2 = prmt_hi(e10, e11);
                uint32_t ph3 = prmt_hi(e12, e13);
                uint32_t pl0 = prmt_hi(e00 - trunc_bf(e00), e01 - trunc_bf(e01));
                uint32_t pl1 = prmt_hi(e02 - trunc_bf(e02), e03 - trunc_bf(e03));
                uint32_t pl2 = prmt_hi(e10 - trunc_bf(e10), e11 - trunc_bf(e11));
                uint32_t pl3 = prmt_hi(e12 - trunc_bf(e12), e13 - trunc_bf(e13));

                // --- O += PhVh + PhVl + PlVh for this 16-key chunk ---
#pragma unroll
                for (int nc2 = 0; nc2 < 4; nc2++) {
                    uint4 vv4 = *(const uint4*)&Vd[nc2 * 8 + g][pc * 32 + tg * 8];
                    mma_bf16(o[f][nc2], ph0, ph1, ph2, ph3, vv4.z, vv4.w);
                    mma_bf16(o[f][nc2], pl0, pl1, pl2, pl3, vv4.x, vv4.y);
                    mma_bf16(o[f][nc2], ph0, ph1, ph2, ph3, vv4.x, vv4.y);
                }
            }
        }
    }

#pragma unroll
    for (int f = 0; f < 2; f++) {
        float l0 = lr[f][0], l1 = lr[f][1];
        l0 += __shfl_xor_sync(0xffffffffu, l0, 1);
        l0 += __shfl_xor_sync(0xffffffffu, l0, 2);
        l1 += __shfl_xor_sync(0xffffffffu, l1, 1);
        l1 += __shfl_xor_sync(0xffffffffu, l1, 2);
        const float inv0 = 1.f / l0;
        const float inv1 = 1.f / l1;
        float* ob = O +
            (size_t)(b * SEQ + qt * 128 + wid * 32 + f * 16) * D_MODEL + h * HEAD_DIM;
#pragma unroll
        for (int nc2 = 0; nc2 < 4; nc2++) {
            int col = nc2 * 8 + tg * 2;
            *(float2*)(ob + (size_t)g * D_MODEL + col) =
                make_float2(o[f][nc2][0] * inv0, o[f][nc2][1] * inv0);
            *(float2*)(ob + (size_t)(g + 8) * D_MODEL + col) =
                make_float2(o[f][nc2][2] * inv1, o[f][nc2][3] * inv1);
        }
    }
}

// ---------------------------------------------------------------------------
extern "C" void kernel_launch(void* const* d_in, const int* in_sizes, int n_in,
                              void* d_out, int out_size) {
    const float* q  = (const float*)d_in[0];
    const float* k  = (const float*)d_in[1];
    const float* v  = (const float*)d_in[2];
    const float* m  = (const float*)d_in[3];
    const float* wq = (const float*)d_in[4];
    const float* bq = (const float*)d_in[5];
    const float* wk = (const float*)d_in[6];
    const float* bk = (const float*)d_in[7];
    const float* wv = (const float*)d_in[8];
    const float* bv = (const float*)d_in[9];
    const float* wo = (const float*)d_in[10];
    const float* bo = (const float*)d_in[11];
    float* out = (float*)d_out;

    float *gQ, *gK, *gV, *gO;
    int *gPos, *gCnt;
    cudaGetSymbolAddress((void**)&gQ, g_Q);
    cudaGetSymbolAddress((void**)&gK, g_K);
    cudaGetSymbolAddress((void**)&gV, g_V);
    cudaGetSymbolAddress((void**)&gO, g_O);
    cudaGetSymbolAddress((void**)&gPos, g_pos);
    cudaGetSymbolAddress((void**)&gCnt, g_cnt);

    scan_mask<<<1, 256>>>(m, gPos, gCnt);

    // Fused QKV projections (grid.z = 3)
    GemmArgs3 qkv;
    qkv.p[0] = {q, wq, bq, gQ, nullptr};
    qkv.p[1] = {k, wk, bk, gK, gPos};
    qkv.p[2] = {v, wv, bv, gV, gPos};
    dim3 qkv_grid(D_MODEL / 64, M_TOTAL / 128, 3);
    gemm_tf32<<<qkv_grid, 128>>>(qkv);

    dim3 attn_grid(SEQ / 128, BATCH * N_HEADS);   // (16, 64)
    flash_mma<<<attn_grid, 128>>>(gQ, gK, gV, gCnt, gO);

    // Output projection
    GemmArgs3 op;
    op.p[0] = {gO, wo, bo, out, nullptr};
    op.p[1] = op.p[0];
    op.p[2] = op.p[0];
    dim3 out_grid(D_MODEL / 64, M_TOTAL / 128, 1);
    gemm_tf32<<<out_grid, 128>>>(op);
}

// round 8
// speedup vs baseline: 1.4539x; 1.4539x over previous
#include <cuda_runtime.h>
#include <cuda_bf16.h>
#include <math.h>
#include <stdint.h>

#define D_MODEL 256
#define N_HEADS 8
#define HEAD_DIM 32
#define BATCH 8
#define SEQ 2048
#define M_TOTAL (BATCH * SEQ)  // 16384

// Scratch (alloc-free rule: __device__ globals)
__device__ float g_Q[M_TOTAL * D_MODEL];
__device__ float g_K[M_TOTAL * D_MODEL];   // compacted keys
__device__ float g_V[M_TOTAL * D_MODEL];   // compacted values
__device__ float g_O[M_TOTAL * D_MODEL];
__device__ int g_pos[SEQ];                 // token -> compact slot (-1 = masked)
__device__ int g_cnt[1];                   // number of kept keys

// ---------------------------------------------------------------------------
// helpers
// ---------------------------------------------------------------------------
__device__ __forceinline__ uint32_t f2tf(float x) {
    uint32_t r;
    asm("cvt.rna.tf32.f32 %0, %1;" : "=r"(r) : "f"(x));
    return r;
}

__device__ __forceinline__ void mma_tf32(float* c, uint32_t a0, uint32_t a1,
                                         uint32_t a2, uint32_t a3,
                                         uint32_t b0, uint32_t b1) {
    asm volatile(
        "mma.sync.aligned.m16n8k8.row.col.f32.tf32.tf32.f32 "
        "{%0,%1,%2,%3}, {%4,%5,%6,%7}, {%8,%9}, {%0,%1,%2,%3};"
        : "+f"(c[0]), "+f"(c[1]), "+f"(c[2]), "+f"(c[3])
        : "r"(a0), "r"(a1), "r"(a2), "r"(a3), "r"(b0), "r"(b1));
}

__device__ __forceinline__ void mma_bf16(float* c, uint32_t a0, uint32_t a1,
                                         uint32_t a2, uint32_t a3,
                                         uint32_t b0, uint32_t b1) {
    asm volatile(
        "mma.sync.aligned.m16n8k16.row.col.f32.bf16.bf16.f32 "
        "{%0,%1,%2,%3}, {%4,%5,%6,%7}, {%8,%9}, {%0,%1,%2,%3};"
        : "+f"(c[0]), "+f"(c[1]), "+f"(c[2]), "+f"(c[3])
        : "r"(a0), "r"(a1), "r"(a2), "r"(a3), "r"(b0), "r"(b1));
}

// prmt: pack high halves of two f32 -> bf16x2 (lo arg -> low half)
__device__ __forceinline__ uint32_t prmt_hi(float lo, float hi) {
    uint32_t r;
    asm("prmt.b32 %0, %1, %2, 0x7632;"
        : "=r"(r) : "r"(__float_as_uint(lo)), "r"(__float_as_uint(hi)));
    return r;
}

__device__ __forceinline__ float ex2(float x) {
    float r;
    asm("ex2.approx.ftz.f32 %0, %1;" : "=f"(r) : "f"(x));
    return r;
}

__device__ __forceinline__ float trunc_bf(float x) {
    return __uint_as_float(__float_as_uint(x) & 0xFFFF0000u);
}

// ---------------------------------------------------------------------------
// Mask scan: pos[s] = compact index for kept keys (-1 masked), cnt = total.
// ---------------------------------------------------------------------------
__global__ __launch_bounds__(256) void scan_mask(const float* __restrict__ m,
                                                 int* __restrict__ pos,
                                                 int* __restrict__ cnt) {
    __shared__ int warpsum[8];
    const int tid = threadIdx.x;
    int keep[8], local[8], s = 0;
#pragma unroll
    for (int i = 0; i < 8; i++) {
        keep[i] = (m[tid * 8 + i] == 0.0f) ? 1 : 0;
        local[i] = s;
        s += keep[i];
    }
    const int lane = tid & 31, w = tid >> 5;
    int x = s;
#pragma unroll
    for (int d = 1; d < 32; d <<= 1) {
        int y = __shfl_up_sync(0xffffffffu, x, d);
        if (lane >= d) x += y;
    }
    if (lane == 31) warpsum[w] = x;
    __syncthreads();
    if (tid == 0) {
        int a = 0;
#pragma unroll
        for (int i = 0; i < 8; i++) {
            int t = warpsum[i];
            warpsum[i] = a;
            a += t;
        }
        *cnt = a;
    }
    __syncthreads();
    const int off = warpsum[w] + x - s;
#pragma unroll
    for (int i = 0; i < 8; i++)
        pos[tid * 8 + i] = keep[i] ? off + local[i] : -1;
}

// ---------------------------------------------------------------------------
// GEMM (R6, measured 37.8us): C[M,256] = A[M,256] @ W[256,256] + bias.
// 2-term asymmetric split: A single tf32, W split hi/lo (interleaved float2).
// Block tile 128x64, k-stage 32, 4 warps. Optional row remap (scatter/drop).
// ---------------------------------------------------------------------------
__global__ __launch_bounds__(128) void gemm_tf32(const float* __restrict__ A,
                                                 const float* __restrict__ W,
                                                 const float* __restrict__ bias,
                                                 float* __restrict__ C,
                                                 const int* __restrict__ remap) {
    __shared__ float As[128][36];    // [m][k] single tf32, stride 36
    __shared__ float2 Wd[32][68];    // [k][n] (hi,lo), stride 68 float2

    const int tid = threadIdx.x;
    const int lane = tid & 31;
    const int wid = tid >> 5;
    const int g = lane >> 2;
    const int tg = lane & 3;

    const int m0 = blockIdx.y * 128;
    const int n0 = blockIdx.x * 64;

    float acc[2][8][4];
#pragma unroll
    for (int f = 0; f < 2; f++)
#pragma unroll
        for (int nc = 0; nc < 8; nc++)
#pragma unroll
            for (int i = 0; i < 4; i++) acc[f][nc][i] = 0.f;

    for (int k0 = 0; k0 < 256; k0 += 32) {
        __syncthreads();
        // A tile: 128 rows x 32 k = 1024 float4, 8 per thread
#pragma unroll
        for (int i = 0; i < 8; i++) {
            int f = tid + i * 128;
            int r = f >> 3, c4 = (f & 7) * 4;
            float4 va = *(const float4*)(A + (size_t)(m0 + r) * 256 + k0 + c4);
            As[r][c4 + 0] = __uint_as_float(f2tf(va.x));
            As[r][c4 + 1] = __uint_as_float(f2tf(va.y));
            As[r][c4 + 2] = __uint_as_float(f2tf(va.z));
            As[r][c4 + 3] = __uint_as_float(f2tf(va.w));
        }
        // W tile: 32 k-rows x 64 n = 512 float4, 4 per thread, hi/lo split
#pragma unroll
        for (int i = 0; i < 4; i++) {
            int f = tid + i * 128;
            int rw = f >> 4, cw = (f & 15) * 4;
            float4 vw = *(const float4*)(W + (size_t)(k0 + rw) * 256 + n0 + cw);
            float vh;
            vh = __uint_as_float(f2tf(vw.x));
            Wd[rw][cw + 0] = make_float2(vh, __uint_as_float(f2tf(vw.x - vh)));
            vh = __uint_as_float(f2tf(vw.y));
            Wd[rw][cw + 1] = make_float2(vh, __uint_as_float(f2tf(vw.y - vh)));
            vh = __uint_as_float(f2tf(vw.z));
            Wd[rw][cw + 2] = make_float2(vh, __uint_as_float(f2tf(vw.z - vh)));
            vh = __uint_as_float(f2tf(vw.w));
            Wd[rw][cw + 3] = make_float2(vh, __uint_as_float(f2tf(vw.w - vh)));
        }
        __syncthreads();

#pragma unroll
        for (int kc = 0; kc < 4; kc++) {
            uint32_t a[2][4];
#pragma unroll
            for (int f = 0; f < 2; f++) {
                int r = wid * 32 + f * 16 + g;
                a[f][0] = __float_as_uint(As[r][kc * 8 + tg]);
                a[f][1] = __float_as_uint(As[r + 8][kc * 8 + tg]);
                a[f][2] = __float_as_uint(As[r][kc * 8 + tg + 4]);
                a[f][3] = __float_as_uint(As[r + 8][kc * 8 + tg + 4]);
            }
#pragma unroll
            for (int nc = 0; nc < 8; nc++) {
                float2 w0 = Wd[kc * 8 + tg][nc * 8 + g];
                float2 w1 = Wd[kc * 8 + tg + 4][nc * 8 + g];
                uint32_t bh0 = __float_as_uint(w0.x), bl0 = __float_as_uint(w0.y);
                uint32_t bh1 = __float_as_uint(w1.x), bl1 = __float_as_uint(w1.y);
#pragma unroll
                for (int f = 0; f < 2; f++) {
                    mma_tf32(acc[f][nc], a[f][0], a[f][1], a[f][2], a[f][3], bl0, bl1);
                    mma_tf32(acc[f][nc], a[f][0], a[f][1], a[f][2], a[f][3], bh0, bh1);
                }
            }
        }
    }

#pragma unroll
    for (int f = 0; f < 2; f++) {
        int r0 = m0 + wid * 32 + f * 16 + g;
        int r1 = r0 + 8;
        int d0 = r0, d1 = r1;
        bool st0 = true, st1 = true;
        if (remap) {
            int p0 = __ldg(remap + (r0 & (SEQ - 1)));
            int p1 = __ldg(remap + (r1 & (SEQ - 1)));
            st0 = p0 >= 0;
            st1 = p1 >= 0;
            d0 = (r0 & ~(SEQ - 1)) + p0;
            d1 = (r1 & ~(SEQ - 1)) + p1;
        }
#pragma unroll
        for (int nc = 0; nc < 8; nc++) {
            int col = n0 + nc * 8 + tg * 2;
            float2 bv = *(const float2*)(bias + col);
            if (st0)
                *(float2*)(C + (size_t)d0 * 256 + col) =
                    make_float2(acc[f][nc][0] + bv.x, acc[f][nc][1] + bv.y);
            if (st1)
                *(float2*)(C + (size_t)d1 * 256 + col) =
                    make_float2(acc[f][nc][2] + bv.x, acc[f][nc][3] + bv.y);
        }
    }
}

// ---------------------------------------------------------------------------
// Flash attention over COMPACTED keys, no online softmax.
// Per-pc (16-key) pipeline: score -> exp -> trunc-split pack -> PV, keeping
// only 8+8 live registers for scores/P. Truncation split via PRMT (no CVTs).
// grid = (S/128, B*H), block = 128 (4 warps). Warp: 32 queries (2 m16 frags).
// ---------------------------------------------------------------------------
__global__ __launch_bounds__(128) void flash_mma(const float* __restrict__ Q,
                                                 const float* __restrict__ K,
                                                 const float* __restrict__ V,
                                                 const int* __restrict__ cntp,
                                                 float* __restrict__ O) {
    __shared__ float Ks[64][40];        // [key][dim-permuted] tf32
    __shared__ uint16_t Vd[32][160];    // [dim][key-quad: 4 hi, 4 lo] bf16 bits

    const int tid = threadIdx.x;
    const int lane = tid & 31;
    const int wid = tid >> 5;
    const int g = lane >> 2;
    const int tg = lane & 3;

    const int qt = blockIdx.x;          // 128-query tile
    const int b = blockIdx.y >> 3;
    const int h = blockIdx.y & 7;

    const int cnt = __ldg(cntp);
    const int nt = (cnt + 63) >> 6;

    const float LOG2E = 1.4426950408889634f;
    const float qscale = 0.17677669529663687f * LOG2E;  // 1/sqrt(32)*log2(e)

    // Q fragments (2 M-frags per warp, pre-scaled, tf32)
    uint32_t qf[2][4][4];
#pragma unroll
    for (int f = 0; f < 2; f++) {
        const float* qb = Q +
            (size_t)(b * SEQ + qt * 128 + wid * 32 + f * 16) * D_MODEL + h * HEAD_DIM;
#pragma unroll
        for (int kc = 0; kc < 4; kc++) {
            qf[f][kc][0] = f2tf(qb[(size_t)g * D_MODEL + kc * 8 + tg] * qscale);
            qf[f][kc][1] = f2tf(qb[(size_t)(g + 8) * D_MODEL + kc * 8 + tg] * qscale);
            qf[f][kc][2] = f2tf(qb[(size_t)g * D_MODEL + kc * 8 + tg + 4] * qscale);
            qf[f][kc][3] = f2tf(qb[(size_t)(g + 8) * D_MODEL + kc * 8 + tg + 4] * qscale);
        }
    }

    float o[2][4][4];
#pragma unroll
    for (int f = 0; f < 2; f++)
#pragma unroll
        for (int i = 0; i < 4; i++)
#pragma unroll
            for (int j = 0; j < 4; j++) o[f][i][j] = 0.f;
    float lr[2][2] = {{0.f, 0.f}, {0.f, 0.f}};

    const float* kbase = K + (size_t)b * SEQ * D_MODEL + h * HEAD_DIM;
    const float* vbase = V + (size_t)b * SEQ * D_MODEL + h * HEAD_DIM;

    for (int t = 0; t < nt; t++) {
        __syncthreads();
#pragma unroll
        for (int i = 0; i < 4; i++) {
            int f = tid + i * 128;
            int r = f >> 3, c4 = (f & 7) * 4;
            int key = t * 64 + r;
            float4 kv = make_float4(0.f, 0.f, 0.f, 0.f);
            float4 vv = make_float4(0.f, 0.f, 0.f, 0.f);
            if (key < cnt) {
                kv = *(const float4*)(kbase + (size_t)key * D_MODEL + c4);
                vv = *(const float4*)(vbase + (size_t)key * D_MODEL + c4);
            }
            // K: dim-pair permute: col'(d) = (d&~7) + 2*(d&3) + ((d>>2)&1)
            {
                int hb = (c4 >> 2) & 1;
                int cb = (c4 & ~7) + hb;
                Ks[r][cb + 0] = __uint_as_float(f2tf(kv.x));
                Ks[r][cb + 2] = __uint_as_float(f2tf(kv.y));
                Ks[r][cb + 4] = __uint_as_float(f2tf(kv.z));
                Ks[r][cb + 6] = __uint_as_float(f2tf(kv.w));
            }
            // V: key-permuted column, trunc hi/lo quads (bf16 bits)
            int u = r & 15;
            int col = (r >> 4) * 16 + ((u >> 1) & 3) * 4 + (u & 1) + ((u >> 3) & 1) * 2;
            int nh = (col >> 4) * 32 + (((col >> 2) & 3)) * 8 + (col & 3);
            float vx[4] = {vv.x, vv.y, vv.z, vv.w};
#pragma unroll
            for (int e = 0; e < 4; e++) {
                uint32_t bits = __float_as_uint(vx[e]);
                Vd[c4 + e][nh] = (uint16_t)(bits >> 16);
                float lo = vx[e] - __uint_as_float(bits & 0xFFFF0000u);
                Vd[c4 + e][nh + 4] = (uint16_t)(__float_as_uint(lo) >> 16);
            }
        }
        __syncthreads();

        const bool fix = (t == nt - 1) && (cnt & 63);
#pragma unroll
        for (int f = 0; f < 2; f++) {
#pragma unroll
            for (int pc = 0; pc < 4; pc++) {
                // --- scores for n-chunks 2pc, 2pc+1 ---
                float s0[4] = {0.f, 0.f, 0.f, 0.f};
                float s1[4] = {0.f, 0.f, 0.f, 0.f};
#pragma unroll
                for (int kc = 0; kc < 4; kc++) {
                    uint2 k0 = *(const uint2*)&Ks[(2 * pc) * 8 + g][kc * 8 + tg * 2];
                    mma_tf32(s0, qf[f][kc][0], qf[f][kc][1], qf[f][kc][2],
                             qf[f][kc][3], k0.x, k0.y);
                    uint2 k1 = *(const uint2*)&Ks[(2 * pc + 1) * 8 + g][kc * 8 + tg * 2];
                    mma_tf32(s1, qf[f][kc][0], qf[f][kc][1], qf[f][kc][2],
                             qf[f][kc][3], k1.x, k1.y);
                }
                if (fix) {
                    int key0 = t * 64 + (2 * pc) * 8 + tg * 2;
                    if (key0 >= cnt) { s0[0] = -1e30f; s0[2] = -1e30f; }
                    if (key0 + 1 >= cnt) { s0[1] = -1e30f; s0[3] = -1e30f; }
                    int key1 = key0 + 8;
                    if (key1 >= cnt) { s1[0] = -1e30f; s1[2] = -1e30f; }
                    if (key1 + 1 >= cnt) { s1[1] = -1e30f; s1[3] = -1e30f; }
                }
                // --- exp + trunc-split pack ---
                float e00 = ex2(s0[0]), e01 = ex2(s0[1]);
                float e02 = ex2(s0[2]), e03 = ex2(s0[3]);
                float e10 = ex2(s1[0]), e11 = ex2(s1[1]);
                float e12 = ex2(s1[2]), e13 = ex2(s1[3]);
                lr[f][0] += e00 + e01 + e10 + e11;
                lr[f][1] += e02 + e03 + e12 + e13;
                uint32_t ph0 = prmt_hi(e00, e01);
                uint32_t ph1 = prmt_hi(e02, e03);
                uint32_t ph2 = prmt_hi(e10, e11);
                uint32_t ph3 = prmt_hi(e12, e13);
                uint32_t pl0 = prmt_hi(e00 - trunc_bf(e00), e01 - trunc_bf(e01));
                uint32_t pl1 = prmt_hi(e02 - trunc_bf(e02), e03 - trunc_bf(e03));
                uint32_t pl2 = prmt_hi(e10 - trunc_bf(e10), e11 - trunc_bf(e11));
                uint32_t pl3 = prmt_hi(e12 - trunc_bf(e12), e13 - trunc_bf(e13));

                // --- O += PhVh + PhVl + PlVh for this 16-key chunk ---
#pragma unroll
                for (int nc2 = 0; nc2 < 4; nc2++) {
                    uint4 vv4 = *(const uint4*)&Vd[nc2 * 8 + g][pc * 32 + tg * 8];
                    mma_bf16(o[f][nc2], ph0, ph1, ph2, ph3, vv4.z, vv4.w);
                    mma_bf16(o[f][nc2], pl0, pl1, pl2, pl3, vv4.x, vv4.y);
                    mma_bf16(o[f][nc2], ph0, ph1, ph2, ph3, vv4.x, vv4.y);
                }
            }
        }
    }

#pragma unroll
    for (int f = 0; f < 2; f++) {
        float l0 = lr[f][0], l1 = lr[f][1];
        l0 += __shfl_xor_sync(0xffffffffu, l0, 1);
        l0 += __shfl_xor_sync(0xffffffffu, l0, 2);
        l1 += __shfl_xor_sync(0xffffffffu, l1, 1);
        l1 += __shfl_xor_sync(0xffffffffu, l1, 2);
        const float inv0 = 1.f / l0;
        const float inv1 = 1.f / l1;
        float* ob = O +
            (size_t)(b * SEQ + qt * 128 + wid * 32 + f * 16) * D_MODEL + h * HEAD_DIM;
#pragma unroll
        for (int nc2 = 0; nc2 < 4; nc2++) {
            int col = nc2 * 8 + tg * 2;
            *(float2*)(ob + (size_t)g * D_MODEL + col) =
                make_float2(o[f][nc2][0] * inv0, o[f][nc2][1] * inv0);
            *(float2*)(ob + (size_t)(g + 8) * D_MODEL + col) =
                make_float2(o[f][nc2][2] * inv1, o[f][nc2][3] * inv1);
        }
    }
}

// ---------------------------------------------------------------------------
extern "C" void kernel_launch(void* const* d_in, const int* in_sizes, int n_in,
                              void* d_out, int out_size) {
    const float* q  = (const float*)d_in[0];
    const float* k  = (const float*)d_in[1];
    const float* v  = (const float*)d_in[2];
    const float* m  = (const float*)d_in[3];
    const float* wq = (const float*)d_in[4];
    const float* bq = (const float*)d_in[5];
    const float* wk = (const float*)d_in[6];
    const float* bk = (const float*)d_in[7];
    const float* wv = (const float*)d_in[8];
    const float* bv = (const float*)d_in[9];
    const float* wo = (const float*)d_in[10];
    const float* bo = (const float*)d_in[11];
    float* out = (float*)d_out;

    float *gQ, *gK, *gV, *gO;
    int *gPos, *gCnt;
    cudaGetSymbolAddress((void**)&gQ, g_Q);
    cudaGetSymbolAddress((void**)&gK, g_K);
    cudaGetSymbolAddress((void**)&gV, g_V);
    cudaGetSymbolAddress((void**)&gO, g_O);
    cudaGetSymbolAddress((void**)&gPos, g_pos);
    cudaGetSymbolAddress((void**)&gCnt, g_cnt);

    scan_mask<<<1, 256>>>(m, gPos, gCnt);

    dim3 gemm_grid(D_MODEL / 64, M_TOTAL / 128);  // (4, 128)
    gemm_tf32<<<gemm_grid, 128>>>(q, wq, bq, gQ, nullptr);
    gemm_tf32<<<gemm_grid, 128>>>(k, wk, bk, gK, gPos);
    gemm_tf32<<<gemm_grid, 128>>>(v, wv, bv, gV, gPos);

    dim3 attn_grid(SEQ / 128, BATCH * N_HEADS);   // (16, 64)
    flash_mma<<<attn_grid, 128>>>(gQ, gK, gV, gCnt, gO);

    gemm_tf32<<<gemm_grid, 128>>>(gO, wo, bo, out, nullptr);
}

// round 9
// speedup vs baseline: 2.0744x; 1.4268x over previous
#include <cuda_runtime.h>
#include <cuda_fp16.h>
#include <math.h>
#include <stdint.h>

#define D_MODEL 256
#define N_HEADS 8
#define HEAD_DIM 32
#define BATCH 8
#define SEQ 2048
#define M_TOTAL (BATCH * SEQ)  // 16384

// Scratch (alloc-free rule: __device__ globals)
__device__ float g_Q[M_TOTAL * D_MODEL];
__device__ float g_K[M_TOTAL * D_MODEL];   // compacted keys
__device__ float g_V[M_TOTAL * D_MODEL];   // compacted values
__device__ float g_O[M_TOTAL * D_MODEL];
__device__ int g_pos[SEQ];                 // token -> compact slot (-1 = masked)
__device__ int g_cnt[1];                   // number of kept keys

// ---------------------------------------------------------------------------
// helpers
// ---------------------------------------------------------------------------
__device__ __forceinline__ uint32_t f2tf(float x) {
    uint32_t r;
    asm("cvt.rna.tf32.f32 %0, %1;" : "=r"(r) : "f"(x));
    return r;
}

__device__ __forceinline__ void mma_tf32(float* c, uint32_t a0, uint32_t a1,
                                         uint32_t a2, uint32_t a3,
                                         uint32_t b0, uint32_t b1) {
    asm volatile(
        "mma.sync.aligned.m16n8k8.row.col.f32.tf32.tf32.f32 "
        "{%0,%1,%2,%3}, {%4,%5,%6,%7}, {%8,%9}, {%0,%1,%2,%3};"
        : "+f"(c[0]), "+f"(c[1]), "+f"(c[2]), "+f"(c[3])
        : "r"(a0), "r"(a1), "r"(a2), "r"(a3), "r"(b0), "r"(b1));
}

__device__ __forceinline__ void mma_f16(float* c, uint32_t a0, uint32_t a1,
                                        uint32_t a2, uint32_t a3,
                                        uint32_t b0, uint32_t b1) {
    asm volatile(
        "mma.sync.aligned.m16n8k16.row.col.f32.f16.f16.f32 "
        "{%0,%1,%2,%3}, {%4,%5,%6,%7}, {%8,%9}, {%0,%1,%2,%3};"
        : "+f"(c[0]), "+f"(c[1]), "+f"(c[2]), "+f"(c[3])
        : "r"(a0), "r"(a1), "r"(a2), "r"(a3), "r"(b0), "r"(b1));
}

// pack two f32 -> f16x2 (first arg -> low half)
__device__ __forceinline__ uint32_t pack_f16(float lo, float hi) {
    uint32_t r;
    asm("cvt.rn.f16x2.f32 %0, %1, %2;" : "=r"(r) : "f"(hi), "f"(lo));
    return r;
}

__device__ __forceinline__ float ex2(float x) {
    float r;
    asm("ex2.approx.ftz.f32 %0, %1;" : "=f"(r) : "f"(x));
    return r;
}

// ---------------------------------------------------------------------------
// Mask scan: pos[s] = compact index for kept keys (-1 masked), cnt = total.
// ---------------------------------------------------------------------------
__global__ __launch_bounds__(256) void scan_mask(const float* __restrict__ m,
                                                 int* __restrict__ pos,
                                                 int* __restrict__ cnt) {
    __shared__ int warpsum[8];
    const int tid = threadIdx.x;
    int keep[8], local[8], s = 0;
#pragma unroll
    for (int i = 0; i < 8; i++) {
        keep[i] = (m[tid * 8 + i] == 0.0f) ? 1 : 0;
        local[i] = s;
        s += keep[i];
    }
    const int lane = tid & 31, w = tid >> 5;
    int x = s;
#pragma unroll
    for (int d = 1; d < 32; d <<= 1) {
        int y = __shfl_up_sync(0xffffffffu, x, d);
        if (lane >= d) x += y;
    }
    if (lane == 31) warpsum[w] = x;
    __syncthreads();
    if (tid == 0) {
        int a = 0;
#pragma unroll
        for (int i = 0; i < 8; i++) {
            int t = warpsum[i];
            warpsum[i] = a;
            a += t;
        }
        *cnt = a;
    }
    __syncthreads();
    const int off = warpsum[w] + x - s;
#pragma unroll
    for (int i = 0; i < 8; i++)
        pos[tid * 8 + i] = keep[i] ? off + local[i] : -1;
}

// ---------------------------------------------------------------------------
// GEMM (R8-measured 37.8us, unchanged): C = A @ W + bias.
// 2-term asymmetric split: A single tf32, W split hi/lo (interleaved float2).
// ---------------------------------------------------------------------------
__global__ __launch_bounds__(128) void gemm_tf32(const float* __restrict__ A,
                                                 const float* __restrict__ W,
                                                 const float* __restrict__ bias,
                                                 float* __restrict__ C,
                                                 const int* __restrict__ remap) {
    __shared__ float As[128][36];    // [m][k] single tf32, stride 36
    __shared__ float2 Wd[32][68];    // [k][n] (hi,lo), stride 68 float2

    const int tid = threadIdx.x;
    const int lane = tid & 31;
    const int wid = tid >> 5;
    const int g = lane >> 2;
    const int tg = lane & 3;

    const int m0 = blockIdx.y * 128;
    const int n0 = blockIdx.x * 64;

    float acc[2][8][4];
#pragma unroll
    for (int f = 0; f < 2; f++)
#pragma unroll
        for (int nc = 0; nc < 8; nc++)
#pragma unroll
            for (int i = 0; i < 4; i++) acc[f][nc][i] = 0.f;

    for (int k0 = 0; k0 < 256; k0 += 32) {
        __syncthreads();
#pragma unroll
        for (int i = 0; i < 8; i++) {
            int f = tid + i * 128;
            int r = f >> 3, c4 = (f & 7) * 4;
            float4 va = *(const float4*)(A + (size_t)(m0 + r) * 256 + k0 + c4);
            As[r][c4 + 0] = __uint_as_float(f2tf(va.x));
            As[r][c4 + 1] = __uint_as_float(f2tf(va.y));
            As[r][c4 + 2] = __uint_as_float(f2tf(va.z));
            As[r][c4 + 3] = __uint_as_float(f2tf(va.w));
        }
#pragma unroll
        for (int i = 0; i < 4; i++) {
            int f = tid + i * 128;
            int rw = f >> 4, cw = (f & 15) * 4;
            float4 vw = *(const float4*)(W + (size_t)(k0 + rw) * 256 + n0 + cw);
            float vh;
            vh = __uint_as_float(f2tf(vw.x));
            Wd[rw][cw + 0] = make_float2(vh, __uint_as_float(f2tf(vw.x - vh)));
            vh = __uint_as_float(f2tf(vw.y));
            Wd[rw][cw + 1] = make_float2(vh, __uint_as_float(f2tf(vw.y - vh)));
            vh = __uint_as_float(f2tf(vw.z));
            Wd[rw][cw + 2] = make_float2(vh, __uint_as_float(f2tf(vw.z - vh)));
            vh = __uint_as_float(f2tf(vw.w));
            Wd[rw][cw + 3] = make_float2(vh, __uint_as_float(f2tf(vw.w - vh)));
        }
        __syncthreads();

#pragma unroll
        for (int kc = 0; kc < 4; kc++) {
            uint32_t a[2][4];
#pragma unroll
            for (int f = 0; f < 2; f++) {
                int r = wid * 32 + f * 16 + g;
                a[f][0] = __float_as_uint(As[r][kc * 8 + tg]);
                a[f][1] = __float_as_uint(As[r + 8][kc * 8 + tg]);
                a[f][2] = __float_as_uint(As[r][kc * 8 + tg + 4]);
                a[f][3] = __float_as_uint(As[r + 8][kc * 8 + tg + 4]);
            }
#pragma unroll
            for (int nc = 0; nc < 8; nc++) {
                float2 w0 = Wd[kc * 8 + tg][nc * 8 + g];
                float2 w1 = Wd[kc * 8 + tg + 4][nc * 8 + g];
                uint32_t bh0 = __float_as_uint(w0.x), bl0 = __float_as_uint(w0.y);
                uint32_t bh1 = __float_as_uint(w1.x), bl1 = __float_as_uint(w1.y);
#pragma unroll
                for (int f = 0; f < 2; f++) {
                    mma_tf32(acc[f][nc], a[f][0], a[f][1], a[f][2], a[f][3], bl0, bl1);
                    mma_tf32(acc[f][nc], a[f][0], a[f][1], a[f][2], a[f][3], bh0, bh1);
                }
            }
        }
    }

#pragma unroll
    for (int f = 0; f < 2; f++) {
        int r0 = m0 + wid * 32 + f * 16 + g;
        int r1 = r0 + 8;
        int d0 = r0, d1 = r1;
        bool st0 = true, st1 = true;
        if (remap) {
            int p0 = __ldg(remap + (r0 & (SEQ - 1)));
            int p1 = __ldg(remap + (r1 & (SEQ - 1)));
            st0 = p0 >= 0;
            st1 = p1 >= 0;
            d0 = (r0 & ~(SEQ - 1)) + p0;
            d1 = (r1 & ~(SEQ - 1)) + p1;
        }
#pragma unroll
        for (int nc = 0; nc < 8; nc++) {
            int col = n0 + nc * 8 + tg * 2;
            float2 bv = *(const float2*)(bias + col);
            if (st0)
                *(float2*)(C + (size_t)d0 * 256 + col) =
                    make_float2(acc[f][nc][0] + bv.x, acc[f][nc][1] + bv.y);
            if (st1)
                *(float2*)(C + (size_t)d1 * 256 + col) =
                    make_float2(acc[f][nc][2] + bv.x, acc[f][nc][3] + bv.y);
        }
    }
}

// ---------------------------------------------------------------------------
// Flash attention, full fp16 tensor path (fp16 mantissa == tf32 mantissa).
// QK^T: m16n8k16 f16 (K smem dim-pair-permuted, stride 32 halves -> the
// B-frag LDS.128 tiles all 32 banks exactly). P, V single fp16; PV one mma.
// grid = (S/128, B*H), block = 128 (4 warps). Warp: 32 queries (2 m16 frags).
// ---------------------------------------------------------------------------
__global__ __launch_bounds__(128) void flash_mma(const float* __restrict__ Q,
                                                 const float* __restrict__ K,
                                                 const float* __restrict__ V,
                                                 const int* __restrict__ cntp,
                                                 float* __restrict__ O) {
    __shared__ __half Ks[64 * 32];      // [key][dim-pair-permuted], no pad
    __shared__ __half Vd[32 * 80];      // [dim][key-permuted], stride 80

    const int tid = threadIdx.x;
    const int lane = tid & 31;
    const int wid = tid >> 5;
    const int g = lane >> 2;
    const int tg = lane & 3;

    const int qt = blockIdx.x;          // 128-query tile
    const int b = blockIdx.y >> 3;
    const int h = blockIdx.y & 7;

    const int cnt = __ldg(cntp);
    const int nt = (cnt + 63) >> 6;

    const float LOG2E = 1.4426950408889634f;
    const float qscale = 0.17677669529663687f * LOG2E;  // 1/sqrt(32)*log2(e)

    // Q fragments fp16 (2 M-frags per warp, pre-scaled). a-regs per kc16:
    // a0=(g, 2tg:2tg+1), a1=(g+8, same), a2=(g, 2tg+8:+9), a3=(g+8, same)
    uint32_t qf[2][2][4];
#pragma unroll
    for (int f = 0; f < 2; f++) {
        const float* qb = Q +
            (size_t)(b * SEQ + qt * 128 + wid * 32 + f * 16) * D_MODEL + h * HEAD_DIM;
#pragma unroll
        for (int kc = 0; kc < 2; kc++) {
            float2 q0 = *(const float2*)(qb + (size_t)g * D_MODEL + kc * 16 + 2 * tg);
            float2 q1 = *(const float2*)(qb + (size_t)(g + 8) * D_MODEL + kc * 16 + 2 * tg);
            float2 q2 = *(const float2*)(qb + (size_t)g * D_MODEL + kc * 16 + 8 + 2 * tg);
            float2 q3 = *(const float2*)(qb + (size_t)(g + 8) * D_MODEL + kc * 16 + 8 + 2 * tg);
            qf[f][kc][0] = pack_f16(q0.x * qscale, q0.y * qscale);
            qf[f][kc][1] = pack_f16(q1.x * qscale, q1.y * qscale);
            qf[f][kc][2] = pack_f16(q2.x * qscale, q2.y * qscale);
            qf[f][kc][3] = pack_f16(q3.x * qscale, q3.y * qscale);
        }
    }

    float o[2][4][4];
#pragma unroll
    for (int f = 0; f < 2; f++)
#pragma unroll
        for (int i = 0; i < 4; i++)
#pragma unroll
            for (int j = 0; j < 4; j++) o[f][i][j] = 0.f;
    float lr[2][2] = {{0.f, 0.f}, {0.f, 0.f}};

    const float* kbase = K + (size_t)b * SEQ * D_MODEL + h * HEAD_DIM;
    const float* vbase = V + (size_t)b * SEQ * D_MODEL + h * HEAD_DIM;

    for (int t = 0; t < nt; t++) {
        __syncthreads();
#pragma unroll
        for (int i = 0; i < 4; i++) {
            int f = tid + i * 128;
            int r = f >> 3, c4 = (f & 7) * 4;
            int key = t * 64 + r;
            float4 kv = make_float4(0.f, 0.f, 0.f, 0.f);
            float4 vv = make_float4(0.f, 0.f, 0.f, 0.f);
            if (key < cnt) {
                kv = *(const float4*)(kbase + (size_t)key * D_MODEL + c4);
                vv = *(const float4*)(vbase + (size_t)key * D_MODEL + c4);
            }
            // K: dim-pair permute pos(p) = (p&3)*4 + (p>>2); row stride 32 halves
            {
                int p0 = c4 >> 1;  // even
                int pos0 = (p0 & 3) * 4 + (p0 >> 2);
                int pos1 = ((p0 + 1) & 3) * 4 + ((p0 + 1) >> 2);
                *(uint32_t*)&Ks[r * 32 + pos0 * 2] = pack_f16(kv.x, kv.y);
                *(uint32_t*)&Ks[r * 32 + pos1 * 2] = pack_f16(kv.z, kv.w);
            }
            // V: transposed [dim][key-permuted], stride 80 halves
            {
                int grp = r >> 4, u = r & 15, kp = u >> 1, odd = u & 1;
                int phi = grp * 16 + ((kp & 3) * 2 + (kp >> 2)) * 2 + odd;
                Vd[(c4 + 0) * 80 + phi] = __float2half_rn(vv.x);
                Vd[(c4 + 1) * 80 + phi] = __float2half_rn(vv.y);
                Vd[(c4 + 2) * 80 + phi] = __float2half_rn(vv.z);
                Vd[(c4 + 3) * 80 + phi] = __float2half_rn(vv.w);
            }
        }
        __syncthreads();

        const bool fix = (t == nt - 1) && (cnt & 63);
#pragma unroll
        for (int pc = 0; pc < 4; pc++) {
            // K B-frags for the two 8-key chunks (shared by both M-frags)
            uint4 kf0 = *(const uint4*)&Ks[(pc * 16 + g) * 32 + 8 * tg];
            uint4 kf1 = *(const uint4*)&Ks[(pc * 16 + 8 + g) * 32 + 8 * tg];

            uint32_t ph[2][4];
#pragma unroll
            for (int f = 0; f < 2; f++) {
                float s0[4] = {0.f, 0.f, 0.f, 0.f};
                float s1[4] = {0.f, 0.f, 0.f, 0.f};
                mma_f16(s0, qf[f][0][0], qf[f][0][1], qf[f][0][2], qf[f][0][3],
                        kf0.x, kf0.y);
                mma_f16(s0, qf[f][1][0], qf[f][1][1], qf[f][1][2], qf[f][1][3],
                        kf0.z, kf0.w);
                mma_f16(s1, qf[f][0][0], qf[f][0][1], qf[f][0][2], qf[f][0][3],
                        kf1.x, kf1.y);
                mma_f16(s1, qf[f][1][0], qf[f][1][1], qf[f][1][2], qf[f][1][3],
                        kf1.z, kf1.w);
                if (fix) {
                    int key0 = t * 64 + pc * 16 + 2 * tg;
                    if (key0 >= cnt) { s0[0] = -1e30f; s0[2] = -1e30f; }
                    if (key0 + 1 >= cnt) { s0[1] = -1e30f; s0[3] = -1e30f; }
                    int key1 = key0 + 8;
                    if (key1 >= cnt) { s1[0] = -1e30f; s1[2] = -1e30f; }
                    if (key1 + 1 >= cnt) { s1[1] = -1e30f; s1[3] = -1e30f; }
                }
                float e00 = ex2(s0[0]), e01 = ex2(s0[1]);
                float e02 = ex2(s0[2]), e03 = ex2(s0[3]);
                float e10 = ex2(s1[0]), e11 = ex2(s1[1]);
                float e12 = ex2(s1[2]), e13 = ex2(s1[3]);
                lr[f][0] += e00 + e01 + e10 + e11;
                lr[f][1] += e02 + e03 + e12 + e13;
                ph[f][0] = pack_f16(e00, e01);
                ph[f][1] = pack_f16(e02, e03);
                ph[f][2] = pack_f16(e10, e11);
                ph[f][3] = pack_f16(e12, e13);
            }

            // PV: one fp16 mma per (f, nc2); V frags shared across f
#pragma unroll
            for (int nc2 = 0; nc2 < 4; nc2++) {
                uint2 vb = *(const uint2*)&Vd[(nc2 * 8 + g) * 80 + pc * 16 + 4 * tg];
                mma_f16(o[0][nc2], ph[0][0], ph[0][1], ph[0][2], ph[0][3],
                        vb.x, vb.y);
                mma_f16(o[1][nc2], ph[1][0], ph[1][1], ph[1][2], ph[1][3],
                        vb.x, vb.y);
            }
        }
    }

#pragma unroll
    for (int f = 0; f < 2; f++) {
        float l0 = lr[f][0], l1 = lr[f][1];
        l0 += __shfl_xor_sync(0xffffffffu, l0, 1);
        l0 += __shfl_xor_sync(0xffffffffu, l0, 2);
        l1 += __shfl_xor_sync(0xffffffffu, l1, 1);
        l1 += __shfl_xor_sync(0xffffffffu, l1, 2);
        const float inv0 = 1.f / l0;
        const float inv1 = 1.f / l1;
        float* ob = O +
            (size_t)(b * SEQ + qt * 128 + wid * 32 + f * 16) * D_MODEL + h * HEAD_DIM;
#pragma unroll
        for (int nc2 = 0; nc2 < 4; nc2++) {
            int col = nc2 * 8 + tg * 2;
            *(float2*)(ob + (size_t)g * D_MODEL + col) =
                make_float2(o[f][nc2][0] * inv0, o[f][nc2][1] * inv0);
            *(float2*)(ob + (size_t)(g + 8) * D_MODEL + col) =
                make_float2(o[f][nc2][2] * inv1, o[f][nc2][3] * inv1);
        }
    }
}

// ---------------------------------------------------------------------------
extern "C" void kernel_launch(void* const* d_in, const int* in_sizes, int n_in,
                              void* d_out, int out_size) {
    const float* q  = (const float*)d_in[0];
    const float* k  = (const float*)d_in[1];
    const float* v  = (const float*)d_in[2];
    const float* m  = (const float*)d_in[3];
    const float* wq = (const float*)d_in[4];
    const float* bq = (const float*)d_in[5];
    const float* wk = (const float*)d_in[6];
    const float* bk = (const float*)d_in[7];
    const float* wv = (const float*)d_in[8];
    const float* bv = (const float*)d_in[9];
    const float* wo = (const float*)d_in[10];
    const float* bo = (const float*)d_in[11];
    float* out = (float*)d_out;

    float *gQ, *gK, *gV, *gO;
    int *gPos, *gCnt;
    cudaGetSymbolAddress((void**)&gQ, g_Q);
    cudaGetSymbolAddress((void**)&gK, g_K);
    cudaGetSymbolAddress((void**)&gV, g_V);
    cudaGetSymbolAddress((void**)&gO, g_O);
    cudaGetSymbolAddress((void**)&gPos, g_pos);
    cudaGetSymbolAddress((void**)&gCnt, g_cnt);

    scan_mask<<<1, 256>>>(m, gPos, gCnt);

    dim3 gemm_grid(D_MODEL / 64, M_TOTAL / 128);  // (4, 128)
    gemm_tf32<<<gemm_grid, 128>>>(q, wq, bq, gQ, nullptr);
    gemm_tf32<<<gemm_grid, 128>>>(k, wk, bk, gK, gPos);
    gemm_tf32<<<gemm_grid, 128>>>(v, wv, bv, gV, gPos);

    dim3 attn_grid(SEQ / 128, BATCH * N_HEADS);   // (16, 64)
    flash_mma<<<attn_grid, 128>>>(gQ, gK, gV, gCnt, gO);

    gemm_tf32<<<gemm_grid, 128>>>(gO, wo, bo, out, nullptr);
}